// round 12
// baseline (speedup 1.0000x reference)
#include <cuda_runtime.h>
#include <cstdint>

// Base-10 addition of digit arrays (B=524288 rows x 64 digits), exact fp32.
//
// Geometry (best-measured): 16 lanes per row, each lane owns a contiguous
// 4-digit segment (one float4). A warp covers 2 rows per "slot"
// (rsel = lane>>4), each thread processes TWO independent slots
// (rows 4w+rsel and 4w+rsel+2): 4 front-batched LDG.128 per thread,
// 3KB per warp, ~31 regs -> full occupancy. Default cache policy
// (streaming hints measured worse: DRAM 85.7% -> 80.3%).
// Block = 512 threads -> 64 consecutive rows = 16KB contiguous per array
// per block for DRAM locality.
//
// Carry resolution per row: each lane ripples its 4 digits twice (carry-in 0
// and 1), yielding segment carry-out bits G (chain0) and G|P (chain1).
// Ballots collect them warp-wide; the 16-segment carry-lookahead is solved
// with the adder identity:
//     decimal carries == binary carries of (G|P) + G
//     carry-in mask M  = P ^ ((G|P) + G),   P = GP & ~G
// Each lane then selects its precomputed digit set. No shuffles.

static constexpr int BATCH   = 524288;
static constexpr int SEQ_LEN = 64;

struct Seg {
    float d00, d01, d02, d03;   // digits, carry-in = 0
    float d10, d11, d12, d13;   // digits, carry-in = 1
    float k0, k1;               // segment carry-outs: G, G|P
};

__device__ __forceinline__ Seg seg_chains(const float4 av, const float4 bv)
{
    Seg r;
    const float s0 = av.w + bv.w;   // integers 0..9 -> all fp32 ops exact
    const float s1 = av.z + bv.z;
    const float s2 = av.y + bv.y;
    const float s3 = av.x + bv.x;

    float t, k;
    t = s0;        k = (t >= 10.f) ? 1.f : 0.f;  r.d00 = fmaf(-10.f, k, t);
    t = s1 + k;    k = (t >= 10.f) ? 1.f : 0.f;  r.d01 = fmaf(-10.f, k, t);
    t = s2 + k;    k = (t >= 10.f) ? 1.f : 0.f;  r.d02 = fmaf(-10.f, k, t);
    t = s3 + k;    k = (t >= 10.f) ? 1.f : 0.f;  r.d03 = fmaf(-10.f, k, t);
    r.k0 = k;

    t = s0 + 1.f;  k = (t >= 10.f) ? 1.f : 0.f;  r.d10 = fmaf(-10.f, k, t);
    t = s1 + k;    k = (t >= 10.f) ? 1.f : 0.f;  r.d11 = fmaf(-10.f, k, t);
    t = s2 + k;    k = (t >= 10.f) ? 1.f : 0.f;  r.d12 = fmaf(-10.f, k, t);
    t = s3 + k;    k = (t >= 10.f) ? 1.f : 0.f;  r.d13 = fmaf(-10.f, k, t);
    r.k1 = k;
    return r;
}

__device__ __forceinline__ float4 seg_select(const Seg& r, bool cin)
{
    float4 ov;
    ov.w = cin ? r.d10 : r.d00;
    ov.z = cin ? r.d11 : r.d01;
    ov.y = cin ? r.d12 : r.d02;
    ov.x = cin ? r.d13 : r.d03;
    return ov;
}

__device__ __forceinline__ bool carry_in(unsigned gmask, unsigned gpmask,
                                         unsigned rsel, unsigned sub)
{
    const unsigned sh  = rsel << 4;
    const unsigned gm  = (gmask  >> sh) & 0xFFFFu;
    const unsigned gpm = (gpmask >> sh) & 0xFFFFu;
    const unsigned pm  = gpm & ~gm;
    const unsigned M   = pm ^ (gpm + gm);   // bit s = carry-in to segment s
    return (M >> sub) & 1u;
}

__global__ __launch_bounds__(512)
void adder_kernel(const float4* __restrict__ a4,
                  const float4* __restrict__ b4,
                  float4* __restrict__ o4)
{
    const unsigned tid  = blockIdx.x * blockDim.x + threadIdx.x;
    const unsigned lane = tid & 31u;
    const unsigned warp = tid >> 5;
    const unsigned sub  = lane & 15u;   // segment index within row (0 = LSB segment)
    const unsigned rsel = lane >> 4;    // which row of the slot

    // Warp covers rows [4w, 4w+3]: slot A = 4w+rsel, slot B = 4w+rsel+2.
    const unsigned rowA = warp * 4u + rsel;
    const unsigned rowB = rowA + 2u;

    // Segment sub owns LSB-first positions [4*sub, 4*sub+3] -> float4 column 15-sub.
    // Within the float4: .w = least significant digit of the segment.
    const unsigned f    = 15u - sub;
    const size_t   idxA = (size_t)rowA * (SEQ_LEN / 4) + f;
    const size_t   idxB = (size_t)rowB * (SEQ_LEN / 4) + f;

    // Front-batched independent loads (MLP_p1 = 4), default cache policy.
    const float4 avA = a4[idxA];
    const float4 bvA = b4[idxA];
    const float4 avB = a4[idxB];
    const float4 bvB = b4[idxB];

    const Seg rA = seg_chains(avA, bvA);
    const Seg rB = seg_chains(avB, bvB);

    const unsigned gmA  = __ballot_sync(0xFFFFFFFFu, rA.k0 != 0.f);
    const unsigned gpmA = __ballot_sync(0xFFFFFFFFu, rA.k1 != 0.f);
    const unsigned gmB  = __ballot_sync(0xFFFFFFFFu, rB.k0 != 0.f);
    const unsigned gpmB = __ballot_sync(0xFFFFFFFFu, rB.k1 != 0.f);

    o4[idxA] = seg_select(rA, carry_in(gmA, gpmA, rsel, sub));
    o4[idxB] = seg_select(rB, carry_in(gmB, gpmB, rsel, sub));
}

extern "C" void kernel_launch(void* const* d_in, const int* in_sizes, int n_in,
                              void* d_out, int out_size)
{
    const float4* a = (const float4*)d_in[0];
    const float4* b = (const float4*)d_in[1];
    // d_in[2..5] = weight_ih, weight_hh, bias_ih, bias_hh — hardcoded
    // (1,1,0,0) in the reference; semantics folded into the adder.
    float4* out = (float4*)d_out;

    const int total_threads = (BATCH / 4) * 32;   // 4 rows per warp (2 slots x 2 rows)
    const int block = 512;
    const int grid  = total_threads / block;      // divides exactly: 8192
    adder_kernel<<<grid, block>>>(a, b, out);
}

// round 13
// speedup vs baseline: 1.0041x; 1.0041x over previous
#include <cuda_runtime.h>
#include <cstdint>

// Base-10 addition of digit arrays (B=524288 rows x 64 digits), exact fp32.
// FROZEN best configuration (session summary in commit trail):
//   - ballot-based carry-lookahead (no shuffles)      [R2: 78 -> 62 us]
//   - float4 I/O, 16 lanes/row, ILP-2 over row slots  [R3: DRAM 83 -> 86%]
//   - ILP-4 rejected (regs 44, occ 50%, DRAM -2%)     [R4]
//   - __ldcs/__stcs rejected (DRAM 86 -> 80%)         [R9]
//   - block=512: best profile, DRAM 86.1% @ 6.82TB/s  [R12]
// At the B300 LTS/HBM streaming ceiling; bench deltas below ~0.7us are
// timer-tick quantization.
//
// Geometry: each lane owns a contiguous 4-digit segment (one float4).
// A warp covers 2 rows per "slot" (rsel = lane>>4); each thread processes
// TWO independent slots (rows 4w+rsel and 4w+rsel+2): 4 front-batched
// LDG.128 per thread, 3KB per warp, 31 regs.
//
// Carry resolution per row: each lane ripples its 4 digits twice (carry-in
// 0 and 1) giving segment carry-outs G (chain0) and G|P (chain1); two
// ballots collect them and the 16-segment lookahead is solved with the
// adder identity:
//     decimal carries == binary carries of (G|P) + G
//     carry-in mask M  = P ^ ((G|P) + G),   P = GP & ~G
// All arithmetic is exact in fp32 for digits 0..9 -> rel_err == 0.

static constexpr int BATCH   = 524288;
static constexpr int SEQ_LEN = 64;

struct Seg {
    float d00, d01, d02, d03;   // digits, carry-in = 0
    float d10, d11, d12, d13;   // digits, carry-in = 1
    float k0, k1;               // segment carry-outs: G, G|P
};

__device__ __forceinline__ Seg seg_chains(const float4 av, const float4 bv)
{
    Seg r;
    const float s0 = av.w + bv.w;   // integers 0..9 -> all fp32 ops exact
    const float s1 = av.z + bv.z;
    const float s2 = av.y + bv.y;
    const float s3 = av.x + bv.x;

    float t, k;
    t = s0;        k = (t >= 10.f) ? 1.f : 0.f;  r.d00 = fmaf(-10.f, k, t);
    t = s1 + k;    k = (t >= 10.f) ? 1.f : 0.f;  r.d01 = fmaf(-10.f, k, t);
    t = s2 + k;    k = (t >= 10.f) ? 1.f : 0.f;  r.d02 = fmaf(-10.f, k, t);
    t = s3 + k;    k = (t >= 10.f) ? 1.f : 0.f;  r.d03 = fmaf(-10.f, k, t);
    r.k0 = k;

    t = s0 + 1.f;  k = (t >= 10.f) ? 1.f : 0.f;  r.d10 = fmaf(-10.f, k, t);
    t = s1 + k;    k = (t >= 10.f) ? 1.f : 0.f;  r.d11 = fmaf(-10.f, k, t);
    t = s2 + k;    k = (t >= 10.f) ? 1.f : 0.f;  r.d12 = fmaf(-10.f, k, t);
    t = s3 + k;    k = (t >= 10.f) ? 1.f : 0.f;  r.d13 = fmaf(-10.f, k, t);
    r.k1 = k;
    return r;
}

__device__ __forceinline__ float4 seg_select(const Seg& r, bool cin)
{
    float4 ov;
    ov.w = cin ? r.d10 : r.d00;
    ov.z = cin ? r.d11 : r.d01;
    ov.y = cin ? r.d12 : r.d02;
    ov.x = cin ? r.d13 : r.d03;
    return ov;
}

__device__ __forceinline__ bool carry_in(unsigned gmask, unsigned gpmask,
                                         unsigned rsel, unsigned sub)
{
    const unsigned sh  = rsel << 4;
    const unsigned gm  = (gmask  >> sh) & 0xFFFFu;
    const unsigned gpm = (gpmask >> sh) & 0xFFFFu;
    const unsigned pm  = gpm & ~gm;
    const unsigned M   = pm ^ (gpm + gm);   // bit s = carry-in to segment s
    return (M >> sub) & 1u;
}

__global__ __launch_bounds__(512)
void adder_kernel(const float4* __restrict__ a4,
                  const float4* __restrict__ b4,
                  float4* __restrict__ o4)
{
    const unsigned tid  = blockIdx.x * blockDim.x + threadIdx.x;
    const unsigned lane = tid & 31u;
    const unsigned warp = tid >> 5;
    const unsigned sub  = lane & 15u;   // segment index within row (0 = LSB segment)
    const unsigned rsel = lane >> 4;    // which row of the slot

    // Warp covers rows [4w, 4w+3]: slot A = 4w+rsel, slot B = 4w+rsel+2.
    const unsigned rowA = warp * 4u + rsel;
    const unsigned rowB = rowA + 2u;

    // Segment sub owns LSB-first positions [4*sub, 4*sub+3] -> float4 column
    // 15-sub; within the float4, .w is the segment's least significant digit.
    const unsigned f    = 15u - sub;
    const size_t   idxA = (size_t)rowA * (SEQ_LEN / 4) + f;
    const size_t   idxB = (size_t)rowB * (SEQ_LEN / 4) + f;

    // Front-batched independent loads (MLP_p1 = 4), default cache policy.
    const float4 avA = a4[idxA];
    const float4 bvA = b4[idxA];
    const float4 avB = a4[idxB];
    const float4 bvB = b4[idxB];

    const Seg rA = seg_chains(avA, bvA);
    const Seg rB = seg_chains(avB, bvB);

    const unsigned gmA  = __ballot_sync(0xFFFFFFFFu, rA.k0 != 0.f);
    const unsigned gpmA = __ballot_sync(0xFFFFFFFFu, rA.k1 != 0.f);
    const unsigned gmB  = __ballot_sync(0xFFFFFFFFu, rB.k0 != 0.f);
    const unsigned gpmB = __ballot_sync(0xFFFFFFFFu, rB.k1 != 0.f);

    o4[idxA] = seg_select(rA, carry_in(gmA, gpmA, rsel, sub));
    o4[idxB] = seg_select(rB, carry_in(gmB, gpmB, rsel, sub));
}

extern "C" void kernel_launch(void* const* d_in, const int* in_sizes, int n_in,
                              void* d_out, int out_size)
{
    const float4* a = (const float4*)d_in[0];
    const float4* b = (const float4*)d_in[1];
    // d_in[2..5] = weight_ih, weight_hh, bias_ih, bias_hh — hardcoded
    // (1,1,0,0) in the reference; semantics folded into the adder.
    float4* out = (float4*)d_out;

    const int total_threads = (BATCH / 4) * 32;   // 4 rows per warp (2 slots x 2 rows)
    const int block = 512;
    const int grid  = total_threads / block;      // divides exactly: 8192
    adder_kernel<<<grid, block>>>(a, b, out);
}

// round 14
// speedup vs baseline: 1.0114x; 1.0073x over previous
#include <cuda_runtime.h>
#include <cstdint>

// Base-10 addition of digit arrays (B=524288 rows x 64 digits), exact fp32.
// Best-known configuration, single change this round: block 512 -> 1024
// (32KB contiguous per array per block; CTA count 8192 -> 4096).
// Session evidence:
//   - ballot-based carry-lookahead (no shuffles)      [R2: 78 -> 62 us]
//   - float4 I/O, 16 lanes/row, ILP-2 over row slots  [R3: DRAM 83 -> 86%]
//   - ILP-4 rejected (regs 44, occ 50%, DRAM -2%)     [R4]
//   - __ldcs/__stcs rejected (DRAM 86 -> 80%)         [R9]
//   - block=512 best so far: DRAM 86.1% @ 6.82TB/s    [R12]
// Bench deltas below ~0.7us are timer-tick quantization.
//
// Geometry: each lane owns a contiguous 4-digit segment (one float4).
// A warp covers 2 rows per "slot" (rsel = lane>>4); each thread processes
// TWO independent slots (rows 4w+rsel and 4w+rsel+2): 4 front-batched
// LDG.128 per thread, 3KB per warp, 31 regs.
//
// Carry resolution per row: each lane ripples its 4 digits twice (carry-in
// 0 and 1) giving segment carry-outs G (chain0) and G|P (chain1); two
// ballots collect them and the 16-segment lookahead is solved with the
// adder identity:
//     decimal carries == binary carries of (G|P) + G
//     carry-in mask M  = P ^ ((G|P) + G),   P = GP & ~G
// All arithmetic is exact in fp32 for digits 0..9 -> rel_err == 0.

static constexpr int BATCH   = 524288;
static constexpr int SEQ_LEN = 64;

struct Seg {
    float d00, d01, d02, d03;   // digits, carry-in = 0
    float d10, d11, d12, d13;   // digits, carry-in = 1
    float k0, k1;               // segment carry-outs: G, G|P
};

__device__ __forceinline__ Seg seg_chains(const float4 av, const float4 bv)
{
    Seg r;
    const float s0 = av.w + bv.w;   // integers 0..9 -> all fp32 ops exact
    const float s1 = av.z + bv.z;
    const float s2 = av.y + bv.y;
    const float s3 = av.x + bv.x;

    float t, k;
    t = s0;        k = (t >= 10.f) ? 1.f : 0.f;  r.d00 = fmaf(-10.f, k, t);
    t = s1 + k;    k = (t >= 10.f) ? 1.f : 0.f;  r.d01 = fmaf(-10.f, k, t);
    t = s2 + k;    k = (t >= 10.f) ? 1.f : 0.f;  r.d02 = fmaf(-10.f, k, t);
    t = s3 + k;    k = (t >= 10.f) ? 1.f : 0.f;  r.d03 = fmaf(-10.f, k, t);
    r.k0 = k;

    t = s0 + 1.f;  k = (t >= 10.f) ? 1.f : 0.f;  r.d10 = fmaf(-10.f, k, t);
    t = s1 + k;    k = (t >= 10.f) ? 1.f : 0.f;  r.d11 = fmaf(-10.f, k, t);
    t = s2 + k;    k = (t >= 10.f) ? 1.f : 0.f;  r.d12 = fmaf(-10.f, k, t);
    t = s3 + k;    k = (t >= 10.f) ? 1.f : 0.f;  r.d13 = fmaf(-10.f, k, t);
    r.k1 = k;
    return r;
}

__device__ __forceinline__ float4 seg_select(const Seg& r, bool cin)
{
    float4 ov;
    ov.w = cin ? r.d10 : r.d00;
    ov.z = cin ? r.d11 : r.d01;
    ov.y = cin ? r.d12 : r.d02;
    ov.x = cin ? r.d13 : r.d03;
    return ov;
}

__device__ __forceinline__ bool carry_in(unsigned gmask, unsigned gpmask,
                                         unsigned rsel, unsigned sub)
{
    const unsigned sh  = rsel << 4;
    const unsigned gm  = (gmask  >> sh) & 0xFFFFu;
    const unsigned gpm = (gpmask >> sh) & 0xFFFFu;
    const unsigned pm  = gpm & ~gm;
    const unsigned M   = pm ^ (gpm + gm);   // bit s = carry-in to segment s
    return (M >> sub) & 1u;
}

__global__ __launch_bounds__(1024)
void adder_kernel(const float4* __restrict__ a4,
                  const float4* __restrict__ b4,
                  float4* __restrict__ o4)
{
    const unsigned tid  = blockIdx.x * blockDim.x + threadIdx.x;
    const unsigned lane = tid & 31u;
    const unsigned warp = tid >> 5;
    const unsigned sub  = lane & 15u;   // segment index within row (0 = LSB segment)
    const unsigned rsel = lane >> 4;    // which row of the slot

    // Warp covers rows [4w, 4w+3]: slot A = 4w+rsel, slot B = 4w+rsel+2.
    const unsigned rowA = warp * 4u + rsel;
    const unsigned rowB = rowA + 2u;

    // Segment sub owns LSB-first positions [4*sub, 4*sub+3] -> float4 column
    // 15-sub; within the float4, .w is the segment's least significant digit.
    const unsigned f    = 15u - sub;
    const size_t   idxA = (size_t)rowA * (SEQ_LEN / 4) + f;
    const size_t   idxB = (size_t)rowB * (SEQ_LEN / 4) + f;

    // Front-batched independent loads (MLP_p1 = 4), default cache policy.
    const float4 avA = a4[idxA];
    const float4 bvA = b4[idxA];
    const float4 avB = a4[idxB];
    const float4 bvB = b4[idxB];

    const Seg rA = seg_chains(avA, bvA);
    const Seg rB = seg_chains(avB, bvB);

    const unsigned gmA  = __ballot_sync(0xFFFFFFFFu, rA.k0 != 0.f);
    const unsigned gpmA = __ballot_sync(0xFFFFFFFFu, rA.k1 != 0.f);
    const unsigned gmB  = __ballot_sync(0xFFFFFFFFu, rB.k0 != 0.f);
    const unsigned gpmB = __ballot_sync(0xFFFFFFFFu, rB.k1 != 0.f);

    o4[idxA] = seg_select(rA, carry_in(gmA, gpmA, rsel, sub));
    o4[idxB] = seg_select(rB, carry_in(gmB, gpmB, rsel, sub));
}

extern "C" void kernel_launch(void* const* d_in, const int* in_sizes, int n_in,
                              void* d_out, int out_size)
{
    const float4* a = (const float4*)d_in[0];
    const float4* b = (const float4*)d_in[1];
    // d_in[2..5] = weight_ih, weight_hh, bias_ih, bias_hh — hardcoded
    // (1,1,0,0) in the reference; semantics folded into the adder.
    float4* out = (float4*)d_out;

    const int total_threads = (BATCH / 4) * 32;   // 4 rows per warp (2 slots x 2 rows)
    const int block = 1024;
    const int grid  = total_threads / block;      // divides exactly: 4096
    adder_kernel<<<grid, block>>>(a, b, out);
}